// round 2
// baseline (speedup 1.0000x reference)
#include <cuda_runtime.h>
#include <cuda_bf16.h>
#include <cstdint>

// Problem: x [16, 256, 128, 128] f32.
//  1) weight[b,c] = mean over H,W
//  2) idx[b,:] = argsort(weight[b]) ascending, take first 16 (stable)
//  3) out[b,k,:,:] = x[b, idx[b,k], :, :]
//
// HBM-bound: 256 MiB read + 16 MiB read + 16 MiB write ≈ 288 MiB.
// R2: select fused into gather (2 kernels total, one less graph node).

#define B 16
#define C 256
#define HW 16384          // 128*128
#define HW4 4096          // HW / 4 (float4 count)
#define K 16

// Scratch (no allocation allowed in kernel_launch)
__device__ float g_weight[B * C];

// ---------------------------------------------------------------------------
// Kernel 1: per-(b,c) mean over 16384 elements. One block per plane.
// 256 threads x 16 float4 each = 64 KB per block. 4 accumulators to decouple
// the add chain from load retirement.
// ---------------------------------------------------------------------------
__global__ __launch_bounds__(256) void mean_kernel(const float* __restrict__ x) {
    const int bc = blockIdx.x;                       // 0..4095
    const float4* __restrict__ p =
        reinterpret_cast<const float4*>(x + (size_t)bc * HW);

    const int t = threadIdx.x;
    float s0 = 0.f, s1 = 0.f, s2 = 0.f, s3 = 0.f;
#pragma unroll
    for (int i = 0; i < 16; i += 4) {
        float4 v0 = __ldg(&p[t + (i + 0) * 256]);
        float4 v1 = __ldg(&p[t + (i + 1) * 256]);
        float4 v2 = __ldg(&p[t + (i + 2) * 256]);
        float4 v3 = __ldg(&p[t + (i + 3) * 256]);
        s0 += (v0.x + v0.y) + (v0.z + v0.w);
        s1 += (v1.x + v1.y) + (v1.z + v1.w);
        s2 += (v2.x + v2.y) + (v2.z + v2.w);
        s3 += (v3.x + v3.y) + (v3.z + v3.w);
    }
    float s = (s0 + s1) + (s2 + s3);

    // warp reduce
#pragma unroll
    for (int off = 16; off > 0; off >>= 1)
        s += __shfl_down_sync(0xFFFFFFFFu, s, off);

    __shared__ float sred[8];
    if ((t & 31) == 0) sred[t >> 5] = s;
    __syncthreads();
    if (t < 8) {
        float v = sred[t];
#pragma unroll
        for (int off = 4; off > 0; off >>= 1)
            v += __shfl_down_sync(0xFFu, v, off);
        if (t == 0) g_weight[bc] = v * (1.0f / (float)HW);
    }
}

// ---------------------------------------------------------------------------
// Kernel 2 (fused select + gather): blockIdx.x = output plane (b*16+k),
// blockIdx.y = split within the plane. Each block recomputes the stable rank
// of every channel of its batch (O(256) per thread, hidden behind DRAM
// latency of co-resident blocks), picks the channel whose rank == k, then
// copies its quarter of the plane with float4.
// ---------------------------------------------------------------------------
__global__ __launch_bounds__(256) void gather_kernel(const float* __restrict__ x,
                                                     float* __restrict__ out) {
    const int plane = blockIdx.x;                    // 0..255
    const int b = plane >> 4;
    const int k = plane & (K - 1);
    const int t = threadIdx.x;

    __shared__ float sw[C];
    __shared__ int sel;
    sw[t] = g_weight[b * C + t];
    __syncthreads();

    const float v = sw[t];
    int rank = 0;
#pragma unroll 8
    for (int j = 0; j < C; ++j) {
        const float u = sw[j];
        rank += (u < v) || (u == v && j < t);
    }
    if (rank == k) sel = t;                          // exactly one thread hits
    __syncthreads();
    const int c = sel;

    const float4* __restrict__ src =
        reinterpret_cast<const float4*>(x + ((size_t)b * C + c) * HW);
    float4* __restrict__ dst =
        reinterpret_cast<float4*>(out + (size_t)plane * HW);

    const int base = blockIdx.y * (HW4 / 4);         // 1024 float4 per split
#pragma unroll
    for (int i = 0; i < 4; ++i) {
        const int o = base + t + i * 256;
        dst[o] = __ldg(&src[o]);
    }
}

// ---------------------------------------------------------------------------
extern "C" void kernel_launch(void* const* d_in, const int* in_sizes, int n_in,
                              void* d_out, int out_size) {
    const float* x = (const float*)d_in[0];
    float* out = (float*)d_out;

    mean_kernel<<<B * C, 256>>>(x);
    gather_kernel<<<dim3(B * K, 4), 256>>>(x, out);
}